// round 13
// baseline (speedup 1.0000x reference)
#include <cuda_runtime.h>
#include <cuda_bf16.h>
#include <math.h>

// Dimensions (fixed by the problem)
#define B_ROWS 512
#define D_IN 5
#define H_DIM 128
#define VF_DIM 256
#define L_SEG 62        // LS-1
#define LAB 10
#define NSTEP 20
#define RB 4            // rows per CTA
#define NCTA (B_ROWS / RB)   // 128
#define NTHR 1024

typedef unsigned long long ull_t;

// Precomputed global scratch (device globals: no allocation allowed)
__device__ float g_W1t[H_DIM * VF_DIM];          // [k=128][c=256]
__device__ float g_W2t[VF_DIM * VF_DIM];         // [k=256][c=256]
__device__ float g_Wm[32 * VF_DIM * H_DIM];      // [idx][v=256][h=128]  4 MB
__device__ float g_bm[32 * H_DIM];               // [idx][h]
__device__ float g_delta[32];                    // interval widths
__device__ int   g_idx[2 * NSTEP];               // 0-based logsig row per eval

// ---------------------------------------------------------------------------
// f32x2 packed-FMA helpers (sm_103a FFMA2 — PTX-only)
// ---------------------------------------------------------------------------
__device__ __forceinline__ ull_t dup2(float x) {
    ull_t r;
    unsigned int u = __float_as_uint(x);
    asm("mov.b64 %0, {%1, %1};" : "=l"(r) : "r"(u));
    return r;
}
__device__ __forceinline__ void fma2(ull_t& acc, ull_t a, ull_t b) {
    asm("fma.rn.f32x2 %0, %1, %2, %0;" : "+l"(acc) : "l"(a), "l"(b));
}
__device__ __forceinline__ void unpk(ull_t v, float& a, float& b) {
    unsigned int lo, hi;
    asm("mov.b64 {%0, %1}, %2;" : "=r"(lo), "=r"(hi) : "l"(v));
    a = __uint_as_float(lo);
    b = __uint_as_float(hi);
}

// ---------------------------------------------------------------------------
// Setup kernel (merged prep + wmeff).  grid = 160 x 256.  All fp32.
// ---------------------------------------------------------------------------
__global__ void __launch_bounds__(256) setup_kernel(
    const float* __restrict__ ts,
    const float* __restrict__ intervals,
    const float* __restrict__ W1,      // [256][128]
    const float* __restrict__ W2,      // [256][256]
    const float* __restrict__ logsig,  // [32][63]
    const float* __restrict__ Wm,      // [7936][256]
    const float* __restrict__ bm)      // [7936]
{
    if (blockIdx.x < 128) {
        __shared__ float ls[32 * L_SEG];
        int h = blockIdx.x;
        int v = threadIdx.x;

        for (int i = threadIdx.x; i < 32 * L_SEG; i += blockDim.x) {
            int row = i / L_SEG, l = i % L_SEG;
            ls[i] = logsig[row * 63 + l + 1];
        }
        __syncthreads();

        float acc[32];
        #pragma unroll
        for (int i = 0; i < 32; i++) acc[i] = 0.0f;

        for (int l = 0; l < L_SEG; l++) {
            float w = __ldg(&Wm[(h * L_SEG + l) * VF_DIM + v]);
            #pragma unroll
            for (int i = 0; i < 32; i++) acc[i] += w * ls[i * L_SEG + l];
        }
        #pragma unroll
        for (int i = 0; i < 32; i++)
            g_Wm[i * (VF_DIM * H_DIM) + v * H_DIM + h] = acc[i];

        if (threadIdx.x < 32) {
            int i = threadIdx.x;
            float s = 0.0f;
            for (int l = 0; l < L_SEG; l++)
                s += __ldg(&bm[h * L_SEG + l]) * ls[i * L_SEG + l];
            g_bm[i * H_DIM + h] = s;
        }
    } else {
        int b = blockIdx.x - 128;              // 0..31
        int gtid = b * 256 + threadIdx.x;      // 0..8191
        int gsz  = 32 * 256;

        for (int i = gtid; i < H_DIM * VF_DIM; i += gsz) {
            int k = i >> 8, c = i & 255;
            g_W1t[i] = W1[c * H_DIM + k];
        }
        for (int i = gtid; i < VF_DIM * VF_DIM; i += gsz) {
            int k = i >> 8, c = i & 255;
            g_W2t[i] = W2[c * VF_DIM + k];
        }
        if (b == 0) {
            if (threadIdx.x < 32)
                g_delta[threadIdx.x] = intervals[threadIdx.x + 1] - intervals[threadIdx.x];
            if (threadIdx.x < 2 * NSTEP) {
                // Replicate reference fp32 exactly
                float t0 = ts[0];
                float dt = (ts[32] - t0) / 20.0f;
                int i = threadIdx.x >> 1;
                float t = t0 + (float)i * dt;
                if (threadIdx.x & 1) t = t + dt;
                int cnt = 0;
                #pragma unroll
                for (int j = 1; j <= 32; j++) cnt += (intervals[j] < t) ? 1 : 0;
                int idx = cnt + 1;
                idx = max(1, min(idx, 32));
                g_idx[threadIdx.x] = idx - 1;
            }
        }
    }
}

// ---------------------------------------------------------------------------
// One k-iter: float4 weight (4 cols), ull2 acts (4 rows), 8 FFMA2.
// ---------------------------------------------------------------------------
__device__ __forceinline__ void mac4(
    float4 w, ulonglong2 av, ull_t acc[4][2])
{
    ull_t d;
    d = dup2(w.x); fma2(acc[0][0], d, av.x); fma2(acc[0][1], d, av.y);
    d = dup2(w.y); fma2(acc[1][0], d, av.x); fma2(acc[1][1], d, av.y);
    d = dup2(w.z); fma2(acc[2][0], d, av.x); fma2(acc[2][1], d, av.y);
    d = dup2(w.w); fma2(acc[3][0], d, av.x); fma2(acc[3][1], d, av.y);
}

// Conflict-free partial store: region per column ci (store AND load clean).
template <int CR4>
__device__ __forceinline__ void store_partials(float* pbase, ull_t acc[4][2])
{
    #pragma unroll
    for (int ci = 0; ci < 4; ci++) {
        float v0, v1, v2, v3;
        unpk(acc[ci][0], v0, v1);
        unpk(acc[ci][1], v2, v3);
        *(float4*)(pbase + ci * CR4) = make_float4(v0, v1, v2, v3);
    }
}

// ---------------------------------------------------------------------------
// Persistent integration kernel: 128 CTAs x 1024 threads, 4 rows per CTA.
// 4c x 4r tiles; S=16 (L1/L2), S=32 (L3); conflict-free partial layout;
// depth-4 global weight pipeline + cross-phase prefetch.
// ---------------------------------------------------------------------------
#define SMEM_FLOATS (32768 + 512 + 512 + 512 + 1024 + 1024 + 16384)  // 210944 B

__global__ void __launch_bounds__(NTHR, 1)
integrate_kernel(const float* __restrict__ x0,     // [512][5]
                 const float* __restrict__ W_in,   // [128][5]
                 const float* __restrict__ b_in,   // [128]
                 const float* __restrict__ b1,     // [256]
                 const float* __restrict__ b2,     // [256]
                 const float* __restrict__ W_out,  // [10][128]
                 const float* __restrict__ b_out,  // [10]
                 const float* __restrict__ ts,
                 float* __restrict__ out)          // [512][10]
{
    extern __shared__ __align__(16) float sm[];
    float* W1s  = sm;                    // 32768 : W1t cached [k][c]
    float* y_s  = W1s + 32768;           // 512   : y   [h=128][r=4]
    float* yt_s = y_s + 512;             // 512
    float* k1_s = yt_s + 512;            // 512
    float* h1_s = k1_s + 512;            // 1024  : [c=256][r=4]
    float* h2_s = h1_s + 1024;           // 1024
    float* p_s  = h2_s + 1024;           // 16384 : split-K partials

    const int tid = threadIdx.x;
    const int r0  = blockIdx.x * RB;
    // Layers 1/2: 64 col-groups (4 cols) x 16 K-slices
    const int cg  = tid & 63;
    const int s   = tid >> 6;            // 0..15
    // Layer 3: 32 col-groups x 32 K-slices
    const int cg3 = tid & 31;
    const int s3  = tid >> 5;            // 0..31

    // Weight base pointers
    const float* wp1 = W1s   + (s * 8)  * VF_DIM + cg * 4;   // k-range 8
    const float* wp2 = g_W2t + (s * 16) * VF_DIM + cg * 4;   // k-range 16
    // wp3 per eval (k-range 8)

    // Partial-store bases (region-per-ci)
    float* pb12 = p_s + s * 1024 + cg * 4;     // + ci*256
    float* pb3  = p_s + s3 * 512 + cg3 * 4;    // + ci*128

    // Cache W1t into shared memory
    for (int i = tid; i < 8192; i += NTHR)
        *(float4*)&W1s[i * 4] = *(const float4*)&g_W1t[i * 4];

    // y0 = x0 @ W_in^T + b_in   (one (h, r) per thread, tid < 512)
    if (tid < 512) {
        int h = tid >> 2, r = tid & 3;
        float acc = __ldg(&b_in[h]);
        #pragma unroll
        for (int d = 0; d < D_IN; d++)
            acc += __ldg(&x0[(r0 + r) * D_IN + d]) * __ldg(&W_in[h * D_IN + d]);
        y_s[tid] = acc;
    }
    const float dt = (ts[32] - ts[0]) / 20.0f;
    __syncthreads();

    for (int step = 0; step < NSTEP; step++) {
        #pragma unroll 1
        for (int phase = 0; phase < 2; phase++) {
            const float* in_s = phase ? yt_s : y_s;
            const int kt = g_idx[2 * step + phase];
            const float* wp3 = g_Wm + kt * (VF_DIM * H_DIM) + (s3 * 8) * H_DIM + cg3 * 4;

            float4 w2buf[4];
            float4 w3buf[4];

            // ==== Layer 1 GEMM: K=128, 16 slices x 8 k (smem w + smem acts) ====
            {
                const float* ap = in_s + (s * 8) * 4;
                ull_t acc[4][2];
                #pragma unroll
                for (int ci = 0; ci < 4; ci++) { acc[ci][0] = 0ull; acc[ci][1] = 0ull; }
                #pragma unroll
                for (int k = 0; k < 8; k++) {
                    float4 w = *(const float4*)(wp1 + k * VF_DIM);
                    ulonglong2 av = *(const ulonglong2*)(ap + k * 4);
                    mac4(w, av, acc);
                }
                store_partials<256>(pb12, acc);
            }
            // Prefetch layer-2 weights (hides L2 latency behind reduce)
            #pragma unroll
            for (int j = 0; j < 4; j++) w2buf[j] = *(const float4*)(wp2 + j * VF_DIM);
            __syncthreads();

            // ==== Reduce 1 (1024 thr, one slot each): bias + relu ====
            {
                int q = tid;
                float a = 0.f;
                #pragma unroll
                for (int ss = 0; ss < 16; ss++)
                    a += p_s[ss * 1024 + q];
                int ci = q >> 8, rem = q & 255;
                int c = (rem >> 2) * 4 + ci, r = rem & 3;
                h1_s[c * 4 + r] = fmaxf(a + __ldg(&b1[c]), 0.f);
            }
            __syncthreads();

            // ==== Layer 2 GEMM: K=256, 16 slices x 16 k, depth-4 w pipe ====
            {
                const float* ap = h1_s + (s * 16) * 4;
                ull_t acc[4][2];
                #pragma unroll
                for (int ci = 0; ci < 4; ci++) { acc[ci][0] = 0ull; acc[ci][1] = 0ull; }
                #pragma unroll
                for (int kb = 0; kb < 16; kb += 4) {
                    #pragma unroll
                    for (int j = 0; j < 4; j++) {
                        float4 wn = w2buf[j];
                        int nk = kb + 4 + j;
                        if (nk < 16) wn = *(const float4*)(wp2 + nk * VF_DIM);
                        ulonglong2 av = *(const ulonglong2*)(ap + (kb + j) * 4);
                        mac4(w2buf[j], av, acc);
                        w2buf[j] = wn;
                    }
                }
                store_partials<256>(pb12, acc);
            }
            // Prefetch layer-3 weights
            #pragma unroll
            for (int j = 0; j < 4; j++) w3buf[j] = *(const float4*)(wp3 + j * H_DIM);
            __syncthreads();

            // ==== Reduce 2 (1024 thr): bias + tanh ====
            {
                int q = tid;
                float a = 0.f;
                #pragma unroll
                for (int ss = 0; ss < 16; ss++)
                    a += p_s[ss * 1024 + q];
                int ci = q >> 8, rem = q & 255;
                int c = (rem >> 2) * 4 + ci, r = rem & 3;
                h2_s[c * 4 + r] = tanhf(a + __ldg(&b2[c]));
            }
            __syncthreads();

            // ==== Layer 3 GEMM: K=256, 32 slices x 8 k, depth-4 w pipe ====
            {
                const float* ap = h2_s + (s3 * 8) * 4;
                ull_t acc[4][2];
                #pragma unroll
                for (int ci = 0; ci < 4; ci++) { acc[ci][0] = 0ull; acc[ci][1] = 0ull; }
                #pragma unroll
                for (int kb = 0; kb < 8; kb += 4) {
                    #pragma unroll
                    for (int j = 0; j < 4; j++) {
                        float4 wn = w3buf[j];
                        int nk = kb + 4 + j;
                        if (nk < 8) wn = *(const float4*)(wp3 + nk * H_DIM);
                        ulonglong2 av = *(const ulonglong2*)(ap + (kb + j) * 4);
                        mac4(w3buf[j], av, acc);
                        w3buf[j] = wn;
                    }
                }
                store_partials<128>(pb3, acc);
            }
            __syncthreads();

            // ==== Reduce 3 + Heun (tid < 512, one (h,r) each) ====
            if (tid < 512) {
                int q = tid;
                float a = 0.f;
                #pragma unroll
                for (int ss = 0; ss < 32; ss++)
                    a += p_s[ss * 512 + q];
                int ci = q >> 7, rem = q & 127;
                int h = (rem >> 2) * 4 + ci, r = rem & 3;
                float dl  = g_delta[kt];
                float bmv = g_bm[kt * H_DIM + h];
                float d = (a + bmv) / dl;
                int addr = h * 4 + r;
                if (phase == 0) {
                    k1_s[addr] = d;
                    yt_s[addr] = y_s[addr] + dt * d;
                } else {
                    y_s[addr] = y_s[addr] + 0.5f * dt * (k1_s[addr] + d);
                }
            }
            __syncthreads();
        }
    }

    // ---- Output: softmax(y @ W_out^T + b_out), 4 rows x 10 labels ----
    if (tid < RB * LAB) {
        int lab = tid % LAB, r = tid / LAB;
        float acc = __ldg(&b_out[lab]);
        for (int k = 0; k < H_DIM; k++)
            acc += y_s[k * RB + r] * __ldg(&W_out[lab * H_DIM + k]);
        h1_s[r * LAB + lab] = acc;
    }
    __syncthreads();
    if (tid < RB) {
        int r = tid;
        float mx = -1e30f;
        #pragma unroll
        for (int l = 0; l < LAB; l++) mx = fmaxf(mx, h1_s[r * LAB + l]);
        float e[LAB]; float sum = 0.f;
        #pragma unroll
        for (int l = 0; l < LAB; l++) { e[l] = expf(h1_s[r * LAB + l] - mx); sum += e[l]; }
        #pragma unroll
        for (int l = 0; l < LAB; l++) out[(r0 + r) * LAB + l] = e[l] / sum;
    }
}

// ---------------------------------------------------------------------------
extern "C" void kernel_launch(void* const* d_in, const int* in_sizes, int n_in,
                              void* d_out, int out_size)
{
    const float* ts        = (const float*)d_in[0];
    const float* logsig    = (const float*)d_in[1];
    const float* x0        = (const float*)d_in[2];
    const float* intervals = (const float*)d_in[3];
    const float* W_vf1     = (const float*)d_in[4];
    const float* b_vf1     = (const float*)d_in[5];
    const float* W_vf2     = (const float*)d_in[6];
    const float* b_vf2     = (const float*)d_in[7];
    const float* W_m       = (const float*)d_in[8];
    const float* b_m       = (const float*)d_in[9];
    const float* W_in      = (const float*)d_in[10];
    const float* b_in      = (const float*)d_in[11];
    const float* W_out     = (const float*)d_in[12];
    const float* b_out     = (const float*)d_in[13];
    float* out = (float*)d_out;

    size_t smem_bytes = SMEM_FLOATS * sizeof(float);  // 210944 B
    cudaFuncSetAttribute(integrate_kernel,
                         cudaFuncAttributeMaxDynamicSharedMemorySize,
                         (int)smem_bytes);

    setup_kernel<<<160, 256>>>(ts, intervals, W_vf1, W_vf2, logsig, W_m, b_m);
    integrate_kernel<<<NCTA, NTHR, smem_bytes>>>(x0, W_in, b_in, b_vf1, b_vf2,
                                                 W_out, b_out, ts, out);
}

// round 14
// speedup vs baseline: 1.2527x; 1.2527x over previous
#include <cuda_runtime.h>
#include <cuda_bf16.h>
#include <math.h>

// Dimensions (fixed by the problem)
#define B_ROWS 512
#define D_IN 5
#define H_DIM 128
#define VF_DIM 256
#define L_SEG 62        // LS-1
#define LAB 10
#define NSTEP 20
#define RB 4            // rows per CTA
#define NCTA (B_ROWS / RB)   // 128
#define NTHR 512

typedef unsigned long long ull_t;

// Packed weight layouts (device globals; setup kernel fills them):
//   L1/L2 (4 cols/lane): flat = i*2048 + w*128 + kq*16 + cgl*4 + cc
//       where k = i*8 + kq, c = (w*4+cgl)*4 + cc
//   L3   (2 cols/lane): flat = idx*32768 + i*1024 + w*64 + kq*8 + cgl*2 + cc
//       where k = i*8 + kq, h = (w*4+cgl)*2 + cc
__device__ float g_W1p[H_DIM * VF_DIM];          // 32768
__device__ float g_W2p[VF_DIM * VF_DIM];         // 65536
__device__ float g_Wmp[32 * VF_DIM * H_DIM];     // 4 MB
__device__ float g_bm[32 * H_DIM];
__device__ float g_delta[32];
__device__ int   g_idx[2 * NSTEP];

// ---------------------------------------------------------------------------
// f32x2 helpers (sm_103a FFMA2/FADD2 — PTX-only)
// ---------------------------------------------------------------------------
__device__ __forceinline__ ull_t dup2(float x) {
    ull_t r;
    unsigned int u = __float_as_uint(x);
    asm("mov.b64 %0, {%1, %1};" : "=l"(r) : "r"(u));
    return r;
}
__device__ __forceinline__ void fma2(ull_t& acc, ull_t a, ull_t b) {
    asm("fma.rn.f32x2 %0, %1, %2, %0;" : "+l"(acc) : "l"(a), "l"(b));
}
__device__ __forceinline__ ull_t add2(ull_t a, ull_t b) {
    ull_t r;
    asm("add.rn.f32x2 %0, %1, %2;" : "=l"(r) : "l"(a), "l"(b));
    return r;
}
__device__ __forceinline__ void unpk(ull_t v, float& a, float& b) {
    unsigned int lo, hi;
    asm("mov.b64 {%0, %1}, %2;" : "=r"(lo), "=r"(hi) : "l"(v));
    a = __uint_as_float(lo);
    b = __uint_as_float(hi);
}
__device__ __forceinline__ ull_t shfl_xor64(ull_t v, int m) {
    unsigned int lo, hi;
    asm("mov.b64 {%0, %1}, %2;" : "=r"(lo), "=r"(hi) : "l"(v));
    lo = __shfl_xor_sync(0xffffffffu, lo, m);
    hi = __shfl_xor_sync(0xffffffffu, hi, m);
    ull_t r;
    asm("mov.b64 %0, {%1, %2};" : "=l"(r) : "r"(lo), "r"(hi));
    return r;
}

// ---------------------------------------------------------------------------
// Setup kernel.  grid = 160 x 256.  All fp32, packed layouts.
// ---------------------------------------------------------------------------
__global__ void __launch_bounds__(256) setup_kernel(
    const float* __restrict__ ts,
    const float* __restrict__ intervals,
    const float* __restrict__ W1,      // [256][128]
    const float* __restrict__ W2,      // [256][256]
    const float* __restrict__ logsig,  // [32][63]
    const float* __restrict__ Wm,      // [7936][256]
    const float* __restrict__ bm)      // [7936]
{
    if (blockIdx.x < 128) {
        __shared__ float ls[32 * L_SEG];
        int h = blockIdx.x;                    // output col 0..127
        int v = threadIdx.x;                   // k 0..255

        for (int i = threadIdx.x; i < 32 * L_SEG; i += blockDim.x) {
            int row = i / L_SEG, l = i % L_SEG;
            ls[i] = logsig[row * 63 + l + 1];
        }
        __syncthreads();

        float acc[32];
        #pragma unroll
        for (int i = 0; i < 32; i++) acc[i] = 0.0f;

        for (int l = 0; l < L_SEG; l++) {
            float w = __ldg(&Wm[(h * L_SEG + l) * VF_DIM + v]);
            #pragma unroll
            for (int i = 0; i < 32; i++) acc[i] += w * ls[i * L_SEG + l];
        }
        int dst = (v >> 3) * 1024 + (h >> 3) * 64 + (v & 7) * 8
                + ((h >> 1) & 3) * 2 + (h & 1);
        #pragma unroll
        for (int i = 0; i < 32; i++)
            g_Wmp[i * 32768 + dst] = acc[i];

        if (threadIdx.x < 32) {
            int i = threadIdx.x;
            float s = 0.0f;
            for (int l = 0; l < L_SEG; l++)
                s += __ldg(&bm[h * L_SEG + l]) * ls[i * L_SEG + l];
            g_bm[i * H_DIM + h] = s;
        }
    } else {
        int b = blockIdx.x - 128;              // 0..31
        int gtid = b * 256 + threadIdx.x;      // 0..8191
        int gsz  = 32 * 256;

        for (int i = gtid; i < H_DIM * VF_DIM; i += gsz) {
            int k = i >> 8, c = i & 255;
            int d = (k >> 3) * 2048 + (c >> 4) * 128 + (k & 7) * 16
                  + ((c >> 2) & 3) * 4 + (c & 3);
            g_W1p[d] = W1[c * H_DIM + k];
        }
        for (int i = gtid; i < VF_DIM * VF_DIM; i += gsz) {
            int k = i >> 8, c = i & 255;
            int d = (k >> 3) * 2048 + (c >> 4) * 128 + (k & 7) * 16
                  + ((c >> 2) & 3) * 4 + (c & 3);
            g_W2p[d] = W2[c * VF_DIM + k];
        }
        if (b == 0) {
            if (threadIdx.x < 32)
                g_delta[threadIdx.x] = intervals[threadIdx.x + 1] - intervals[threadIdx.x];
            if (threadIdx.x < 2 * NSTEP) {
                // Replicate reference fp32 exactly
                float t0 = ts[0];
                float dt = (ts[32] - t0) / 20.0f;
                int i = threadIdx.x >> 1;
                float t = t0 + (float)i * dt;
                if (threadIdx.x & 1) t = t + dt;
                int cnt = 0;
                #pragma unroll
                for (int j = 1; j <= 32; j++) cnt += (intervals[j] < t) ? 1 : 0;
                int idx = cnt + 1;
                idx = max(1, min(idx, 32));
                g_idx[threadIdx.x] = idx - 1;
            }
        }
    }
}

// One k-iter (4 cols): float4 weight, ull2 acts (4 rows), 8 FFMA2.
__device__ __forceinline__ void mac4(float4 w, ulonglong2 av, ull_t acc[4][2])
{
    ull_t d;
    d = dup2(w.x); fma2(acc[0][0], d, av.x); fma2(acc[0][1], d, av.y);
    d = dup2(w.y); fma2(acc[1][0], d, av.x); fma2(acc[1][1], d, av.y);
    d = dup2(w.z); fma2(acc[2][0], d, av.x); fma2(acc[2][1], d, av.y);
    d = dup2(w.w); fma2(acc[3][0], d, av.x); fma2(acc[3][1], d, av.y);
}
// One k-iter (2 cols) for layer 3.
__device__ __forceinline__ void mac2(float2 w, ulonglong2 av, ull_t m[2][2])
{
    ull_t d;
    d = dup2(w.x); fma2(m[0][0], d, av.x); fma2(m[0][1], d, av.y);
    d = dup2(w.y); fma2(m[1][0], d, av.x); fma2(m[1][1], d, av.y);
}

// Reduce-scatter over 8 in-warp K-slices (kq = lane>>2).
// acc[ci][rp] (8 f32x2).  Rounds: xor16 (ci bit1), xor8 (ci bit0), xor4 (rp).
// Result: lane owns slot ci = ((l>>4)&1)*2 + ((l>>3)&1), rp = (l>>2)&1.
__device__ __forceinline__ ull_t rs8(ull_t acc[4][2], int l)
{
    bool h16 = (l & 16);
    #pragma unroll
    for (int cl = 0; cl < 2; cl++)
        #pragma unroll
        for (int rp = 0; rp < 2; rp++) {
            ull_t snd = h16 ? acc[cl][rp] : acc[cl + 2][rp];
            ull_t kp  = h16 ? acc[cl + 2][rp] : acc[cl][rp];
            acc[cl][rp] = add2(kp, shfl_xor64(snd, 16));
        }
    bool h8 = (l & 8);
    #pragma unroll
    for (int rp = 0; rp < 2; rp++) {
        ull_t snd = h8 ? acc[0][rp] : acc[1][rp];
        ull_t kp  = h8 ? acc[1][rp] : acc[0][rp];
        acc[0][rp] = add2(kp, shfl_xor64(snd, 8));
    }
    bool h4 = (l & 4);
    ull_t snd = h4 ? acc[0][0] : acc[0][1];
    ull_t kp  = h4 ? acc[0][1] : acc[0][0];
    return add2(kp, shfl_xor64(snd, 4));
}

// Reduce-scatter for layer 3: m[ci][rp] (4 f32x2) -> one scalar.
// Slot: ci = (l>>4)&1, r = ((l>>3)&1)*2 + ((l>>2)&1).
__device__ __forceinline__ float rs4(ull_t m[2][2], int l)
{
    bool h16 = (l & 16);
    #pragma unroll
    for (int rp = 0; rp < 2; rp++) {
        ull_t snd = h16 ? m[0][rp] : m[1][rp];
        ull_t kp  = h16 ? m[1][rp] : m[0][rp];
        m[0][rp] = add2(kp, shfl_xor64(snd, 16));
    }
    bool h8 = (l & 8);
    ull_t snd = h8 ? m[0][0] : m[0][1];
    ull_t kp  = h8 ? m[0][1] : m[0][0];
    ull_t f2 = add2(kp, shfl_xor64(snd, 8));
    float f0, f1;
    unpk(f2, f0, f1);
    bool h4 = (l & 4);
    float snf = h4 ? f0 : f1;
    float kpf = h4 ? f1 : f0;
    return kpf + __shfl_xor_sync(0xffffffffu, snf, 4);
}

// ---------------------------------------------------------------------------
// Persistent integration kernel: 128 CTAs x 512 threads, 4 rows per CTA.
// In-warp split-K (8 slices) with shuffle reduce-scatter; 3 barriers/eval.
// ---------------------------------------------------------------------------
#define SMEM_FLOATS (32768 + 512 + 512 + 1024 + 1024 + 4096 + 256 + 256 + 32 + 40)

__global__ void __launch_bounds__(NTHR, 1)
integrate_kernel(const float* __restrict__ x0,     // [512][5]
                 const float* __restrict__ W_in,   // [128][5]
                 const float* __restrict__ b_in,   // [128]
                 const float* __restrict__ b1,     // [256]
                 const float* __restrict__ b2,     // [256]
                 const float* __restrict__ W_out,  // [10][128]
                 const float* __restrict__ b_out,  // [10]
                 const float* __restrict__ ts,
                 float* __restrict__ out)          // [512][10]
{
    extern __shared__ __align__(16) float sm[];
    float* W1s  = sm;                    // 32768 : packed W1
    float* y_s  = W1s + 32768;           // 512   : y   [h=128][r=4]
    float* yt_s = y_s + 512;             // 512
    float* h1_s = yt_s + 512;            // 1024  : [c=256][r=4]
    float* h2_s = h1_s + 1024;           // 1024
    float* bm_s = h2_s + 1024;           // 4096
    float* b1_s = bm_s + 4096;           // 256
    float* b2_s = b1_s + 256;            // 256
    float* dl_s = b2_s + 256;            // 32
    int*   idx_s = (int*)(dl_s + 32);    // 40

    const int tid = threadIdx.x;
    const int r0  = blockIdx.x * RB;
    const int wrp = tid >> 5;            // warp 0..15
    const int l   = tid & 31;
    const int kq  = l >> 2;              // K-slice 0..7
    const int cgl = l & 3;               // col-group within warp

    // Final-slot coordinates after reduce-scatter
    const int ci12 = ((l >> 4) & 1) * 2 + ((l >> 3) & 1);
    const int rp12 = (l >> 2) & 1;
    const int c12  = (wrp * 4 + cgl) * 4 + ci12;        // layer-1/2 column
    const int ci3  = (l >> 4) & 1;
    const int r3   = ((l >> 3) & 1) * 2 + ((l >> 2) & 1);
    const int h3   = (wrp * 4 + cgl) * 2 + ci3;         // layer-3 column

    // Lane bases in packed layouts
    const int wb12 = (wrp * 8 + kq) * 16 + cgl * 4;     // L1/L2: + i*2048
    const int wb3  = (wrp * 8 + kq) * 8 + cgl * 2;      // L3:    + i*1024
    const int ab   = kq * 4;                            // acts:  + i*32

    // Preload smem
    for (int i = tid; i < 8192; i += NTHR)
        *(float4*)&W1s[i * 4] = *(const float4*)&g_W1p[i * 4];
    for (int i = tid; i < 4096; i += NTHR) bm_s[i] = g_bm[i];
    if (tid < 256) { b1_s[tid] = b1[tid]; b2_s[tid] = b2[tid]; }
    if (tid < 32)  dl_s[tid] = g_delta[tid];
    if (tid < 2 * NSTEP) idx_s[tid] = g_idx[tid];

    // y0 = x0 @ W_in^T + b_in   (one (h, r) per thread)
    {
        int h = tid >> 2, r = tid & 3;
        float acc = __ldg(&b_in[h]);
        #pragma unroll
        for (int d = 0; d < D_IN; d++)
            acc += __ldg(&x0[(r0 + r) * D_IN + d]) * __ldg(&W_in[h * D_IN + d]);
        y_s[tid] = acc;
    }
    const float dt = (ts[32] - ts[0]) / 20.0f;
    __syncthreads();

    float k1r = 0.0f;

    for (int step = 0; step < NSTEP; step++) {
        #pragma unroll 1
        for (int phase = 0; phase < 2; phase++) {
            const float* in_s = phase ? yt_s : y_s;
            const int kt = idx_s[2 * step + phase];

            // Prefetch global weights for L2/L3 (hidden behind L1 + rs)
            const float* wp2l = g_W2p + wb12;
            const float* wp3l = g_Wmp + kt * 32768 + wb3;
            float4 w2buf[4];
            float2 w3buf[4];
            #pragma unroll
            for (int j = 0; j < 4; j++) w2buf[j] = *(const float4*)(wp2l + j * 2048);
            #pragma unroll
            for (int j = 0; j < 4; j++) w3buf[j] = *(const float2*)(wp3l + j * 1024);

            // ==== Layer 1: K=128, in-warp split-8, 16 i-iters (smem w+acts) ====
            {
                ull_t acc[4][2];
                #pragma unroll
                for (int ci = 0; ci < 4; ci++) { acc[ci][0] = 0ull; acc[ci][1] = 0ull; }
                const float* wl = W1s + wb12;
                const float* ap = in_s + ab;
                #pragma unroll
                for (int i = 0; i < 16; i++) {
                    float4 w = *(const float4*)(wl + i * 2048);
                    ulonglong2 av = *(const ulonglong2*)(ap + i * 32);
                    mac4(w, av, acc);
                }
                ull_t fin = rs8(acc, l);
                float v0, v1;
                unpk(fin, v0, v1);
                float bb = b1_s[c12];
                *(float2*)&h1_s[c12 * 4 + rp12 * 2] =
                    make_float2(fmaxf(v0 + bb, 0.f), fmaxf(v1 + bb, 0.f));
            }
            __syncthreads();

            // ==== Layer 2: K=256, split-8, 32 i-iters, depth-4 LDG pipe ====
            {
                ull_t acc[4][2];
                #pragma unroll
                for (int ci = 0; ci < 4; ci++) { acc[ci][0] = 0ull; acc[ci][1] = 0ull; }
                const float* ap = h1_s + ab;
                #pragma unroll
                for (int kb = 0; kb < 32; kb += 4) {
                    #pragma unroll
                    for (int j = 0; j < 4; j++) {
                        float4 wn = w2buf[j];
                        int nk = kb + 4 + j;
                        if (nk < 32) wn = *(const float4*)(wp2l + nk * 2048);
                        ulonglong2 av = *(const ulonglong2*)(ap + (kb + j) * 32);
                        mac4(w2buf[j], av, acc);
                        w2buf[j] = wn;
                    }
                }
                ull_t fin = rs8(acc, l);
                float v0, v1;
                unpk(fin, v0, v1);
                float bb = b2_s[c12];
                *(float2*)&h2_s[c12 * 4 + rp12 * 2] =
                    make_float2(tanhf(v0 + bb), tanhf(v1 + bb));
            }
            __syncthreads();

            // ==== Layer 3: K=256, split-8, 32 i-iters (2 cols), + Heun ====
            {
                ull_t m[2][2];
                m[0][0] = 0ull; m[0][1] = 0ull; m[1][0] = 0ull; m[1][1] = 0ull;
                const float* ap = h2_s + ab;
                #pragma unroll
                for (int kb = 0; kb < 32; kb += 4) {
                    #pragma unroll
                    for (int j = 0; j < 4; j++) {
                        float2 wn = w3buf[j];
                        int nk = kb + 4 + j;
                        if (nk < 32) wn = *(const float2*)(wp3l + nk * 1024);
                        ulonglong2 av = *(const ulonglong2*)(ap + (kb + j) * 32);
                        mac2(w3buf[j], av, m);
                        w3buf[j] = wn;
                    }
                }
                float a = rs4(m, l);
                float dl  = dl_s[kt];
                float bmv = bm_s[kt * H_DIM + h3];
                float d = (a + bmv) / dl;
                int addr = h3 * 4 + r3;
                if (phase == 0) {
                    k1r = d;
                    yt_s[addr] = y_s[addr] + dt * d;
                } else {
                    y_s[addr] = y_s[addr] + 0.5f * dt * (k1r + d);
                }
            }
            __syncthreads();
        }
    }

    // ---- Output: softmax(y @ W_out^T + b_out), 4 rows x 10 labels ----
    if (tid < RB * LAB) {
        int lab = tid % LAB, r = tid / LAB;
        float acc = __ldg(&b_out[lab]);
        for (int k = 0; k < H_DIM; k++)
            acc += y_s[k * RB + r] * __ldg(&W_out[lab * H_DIM + k]);
        h1_s[r * LAB + lab] = acc;
    }
    __syncthreads();
    if (tid < RB) {
        int r = tid;
        float mx = -1e30f;
        #pragma unroll
        for (int lq = 0; lq < LAB; lq++) mx = fmaxf(mx, h1_s[r * LAB + lq]);
        float e[LAB]; float sum = 0.f;
        #pragma unroll
        for (int lq = 0; lq < LAB; lq++) { e[lq] = expf(h1_s[r * LAB + lq] - mx); sum += e[lq]; }
        #pragma unroll
        for (int lq = 0; lq < LAB; lq++) out[(r0 + r) * LAB + lq] = e[lq] / sum;
    }
}

// ---------------------------------------------------------------------------
extern "C" void kernel_launch(void* const* d_in, const int* in_sizes, int n_in,
                              void* d_out, int out_size)
{
    const float* ts        = (const float*)d_in[0];
    const float* logsig    = (const float*)d_in[1];
    const float* x0        = (const float*)d_in[2];
    const float* intervals = (const float*)d_in[3];
    const float* W_vf1     = (const float*)d_in[4];
    const float* b_vf1     = (const float*)d_in[5];
    const float* W_vf2     = (const float*)d_in[6];
    const float* b_vf2     = (const float*)d_in[7];
    const float* W_m       = (const float*)d_in[8];
    const float* b_m       = (const float*)d_in[9];
    const float* W_in      = (const float*)d_in[10];
    const float* b_in      = (const float*)d_in[11];
    const float* W_out     = (const float*)d_in[12];
    const float* b_out     = (const float*)d_in[13];
    float* out = (float*)d_out;

    size_t smem_bytes = SMEM_FLOATS * sizeof(float);  // 162,080 B
    cudaFuncSetAttribute(integrate_kernel,
                         cudaFuncAttributeMaxDynamicSharedMemorySize,
                         (int)smem_bytes);

    setup_kernel<<<160, 256>>>(ts, intervals, W_vf1, W_vf2, logsig, W_m, b_m);
    integrate_kernel<<<NCTA, NTHR, smem_bytes>>>(x0, W_in, b_in, b_vf1, b_vf2,
                                                 W_out, b_out, ts, out);
}

// round 15
// speedup vs baseline: 1.3241x; 1.0570x over previous
#include <cuda_runtime.h>
#include <cuda_bf16.h>
#include <math.h>

// Dimensions (fixed by the problem)
#define B_ROWS 512
#define D_IN 5
#define H_DIM 128
#define VF_DIM 256
#define L_SEG 62        // LS-1
#define LAB 10
#define NSTEP 20
#define RB 4            // rows per CTA
#define NCTA (B_ROWS / RB)   // 128
#define NTHR 512

typedef unsigned long long ull_t;

// Packed weight layouts (device globals; setup kernel fills them):
//   L1/L2 (4 cols/lane): flat = i*2048 + w*128 + kq*16 + cgl*4 + cc
//       where k = i*8 + kq, c = (w*4+cgl)*4 + cc
//   L3   (2 cols/lane): flat = idx*32768 + i*1024 + w*64 + kq*8 + cgl*2 + cc
//       where k = i*8 + kq, h = (w*4+cgl)*2 + cc
__device__ float g_W1p[H_DIM * VF_DIM];          // 32768
__device__ float g_W2p[VF_DIM * VF_DIM];         // 65536
__device__ float g_Wmp[32 * VF_DIM * H_DIM];     // 4 MB
__device__ float g_bm[32 * H_DIM];
__device__ float g_delta[32];
__device__ int   g_idx[2 * NSTEP];

// ---------------------------------------------------------------------------
// f32x2 helpers (sm_103a FFMA2/FADD2 — PTX-only)
// ---------------------------------------------------------------------------
__device__ __forceinline__ ull_t dup2(float x) {
    ull_t r;
    unsigned int u = __float_as_uint(x);
    asm("mov.b64 %0, {%1, %1};" : "=l"(r) : "r"(u));
    return r;
}
__device__ __forceinline__ void fma2(ull_t& acc, ull_t a, ull_t b) {
    asm("fma.rn.f32x2 %0, %1, %2, %0;" : "+l"(acc) : "l"(a), "l"(b));
}
__device__ __forceinline__ ull_t add2(ull_t a, ull_t b) {
    ull_t r;
    asm("add.rn.f32x2 %0, %1, %2;" : "=l"(r) : "l"(a), "l"(b));
    return r;
}
__device__ __forceinline__ void unpk(ull_t v, float& a, float& b) {
    unsigned int lo, hi;
    asm("mov.b64 {%0, %1}, %2;" : "=r"(lo), "=r"(hi) : "l"(v));
    a = __uint_as_float(lo);
    b = __uint_as_float(hi);
}
__device__ __forceinline__ ull_t shfl_xor64(ull_t v, int m) {
    unsigned int lo, hi;
    asm("mov.b64 {%0, %1}, %2;" : "=r"(lo), "=r"(hi) : "l"(v));
    lo = __shfl_xor_sync(0xffffffffu, lo, m);
    hi = __shfl_xor_sync(0xffffffffu, hi, m);
    ull_t r;
    asm("mov.b64 %0, {%1, %2};" : "=l"(r) : "r"(lo), "r"(hi));
    return r;
}

// ---------------------------------------------------------------------------
// Setup kernel.  grid = 160 x 256.  All fp32, packed layouts.
// ---------------------------------------------------------------------------
__global__ void __launch_bounds__(256) setup_kernel(
    const float* __restrict__ ts,
    const float* __restrict__ intervals,
    const float* __restrict__ W1,      // [256][128]
    const float* __restrict__ W2,      // [256][256]
    const float* __restrict__ logsig,  // [32][63]
    const float* __restrict__ Wm,      // [7936][256]
    const float* __restrict__ bm)      // [7936]
{
    if (blockIdx.x < 128) {
        __shared__ float ls[32 * L_SEG];
        int h = blockIdx.x;                    // output col 0..127
        int v = threadIdx.x;                   // k 0..255

        for (int i = threadIdx.x; i < 32 * L_SEG; i += blockDim.x) {
            int row = i / L_SEG, l = i % L_SEG;
            ls[i] = logsig[row * 63 + l + 1];
        }
        __syncthreads();

        float acc[32];
        #pragma unroll
        for (int i = 0; i < 32; i++) acc[i] = 0.0f;

        for (int l = 0; l < L_SEG; l++) {
            float w = __ldg(&Wm[(h * L_SEG + l) * VF_DIM + v]);
            #pragma unroll
            for (int i = 0; i < 32; i++) acc[i] += w * ls[i * L_SEG + l];
        }
        int dst = (v >> 3) * 1024 + (h >> 3) * 64 + (v & 7) * 8
                + ((h >> 1) & 3) * 2 + (h & 1);
        #pragma unroll
        for (int i = 0; i < 32; i++)
            g_Wmp[i * 32768 + dst] = acc[i];

        if (threadIdx.x < 32) {
            int i = threadIdx.x;
            float s = 0.0f;
            for (int l = 0; l < L_SEG; l++)
                s += __ldg(&bm[h * L_SEG + l]) * ls[i * L_SEG + l];
            g_bm[i * H_DIM + h] = s;
        }
    } else {
        int b = blockIdx.x - 128;              // 0..31
        int gtid = b * 256 + threadIdx.x;      // 0..8191
        int gsz  = 32 * 256;

        for (int i = gtid; i < H_DIM * VF_DIM; i += gsz) {
            int k = i >> 8, c = i & 255;
            int d = (k >> 3) * 2048 + (c >> 4) * 128 + (k & 7) * 16
                  + ((c >> 2) & 3) * 4 + (c & 3);
            g_W1p[d] = W1[c * H_DIM + k];
        }
        for (int i = gtid; i < VF_DIM * VF_DIM; i += gsz) {
            int k = i >> 8, c = i & 255;
            int d = (k >> 3) * 2048 + (c >> 4) * 128 + (k & 7) * 16
                  + ((c >> 2) & 3) * 4 + (c & 3);
            g_W2p[d] = W2[c * VF_DIM + k];
        }
        if (b == 0) {
            if (threadIdx.x < 32)
                g_delta[threadIdx.x] = intervals[threadIdx.x + 1] - intervals[threadIdx.x];
            if (threadIdx.x < 2 * NSTEP) {
                // Replicate reference fp32 exactly
                float t0 = ts[0];
                float dt = (ts[32] - t0) / 20.0f;
                int i = threadIdx.x >> 1;
                float t = t0 + (float)i * dt;
                if (threadIdx.x & 1) t = t + dt;
                int cnt = 0;
                #pragma unroll
                for (int j = 1; j <= 32; j++) cnt += (intervals[j] < t) ? 1 : 0;
                int idx = cnt + 1;
                idx = max(1, min(idx, 32));
                g_idx[threadIdx.x] = idx - 1;
            }
        }
    }
}

// One k-iter (4 cols): float4 weight, ull2 acts (4 rows), 8 FFMA2.
__device__ __forceinline__ void mac4(float4 w, ulonglong2 av, ull_t acc[4][2])
{
    ull_t d;
    d = dup2(w.x); fma2(acc[0][0], d, av.x); fma2(acc[0][1], d, av.y);
    d = dup2(w.y); fma2(acc[1][0], d, av.x); fma2(acc[1][1], d, av.y);
    d = dup2(w.z); fma2(acc[2][0], d, av.x); fma2(acc[2][1], d, av.y);
    d = dup2(w.w); fma2(acc[3][0], d, av.x); fma2(acc[3][1], d, av.y);
}
// One k-iter (2 cols) for layer 3.
__device__ __forceinline__ void mac2(float2 w, ulonglong2 av, ull_t m[2][2])
{
    ull_t d;
    d = dup2(w.x); fma2(m[0][0], d, av.x); fma2(m[0][1], d, av.y);
    d = dup2(w.y); fma2(m[1][0], d, av.x); fma2(m[1][1], d, av.y);
}

// Reduce-scatter over 8 in-warp K-slices (kq = lane>>2).
// acc[ci][rp] (8 f32x2).  Rounds: xor16 (ci bit1), xor8 (ci bit0), xor4 (rp).
// Result: lane owns slot ci = ((l>>4)&1)*2 + ((l>>3)&1), rp = (l>>2)&1.
__device__ __forceinline__ ull_t rs8(ull_t acc[4][2], int l)
{
    bool h16 = (l & 16);
    #pragma unroll
    for (int cl = 0; cl < 2; cl++)
        #pragma unroll
        for (int rp = 0; rp < 2; rp++) {
            ull_t snd = h16 ? acc[cl][rp] : acc[cl + 2][rp];
            ull_t kp  = h16 ? acc[cl + 2][rp] : acc[cl][rp];
            acc[cl][rp] = add2(kp, shfl_xor64(snd, 16));
        }
    bool h8 = (l & 8);
    #pragma unroll
    for (int rp = 0; rp < 2; rp++) {
        ull_t snd = h8 ? acc[0][rp] : acc[1][rp];
        ull_t kp  = h8 ? acc[1][rp] : acc[0][rp];
        acc[0][rp] = add2(kp, shfl_xor64(snd, 8));
    }
    bool h4 = (l & 4);
    ull_t snd = h4 ? acc[0][0] : acc[0][1];
    ull_t kp  = h4 ? acc[0][1] : acc[0][0];
    return add2(kp, shfl_xor64(snd, 4));
}

// Reduce-scatter for layer 3: m[ci][rp] (4 f32x2) -> one scalar.
// Slot: ci = (l>>4)&1, r = ((l>>3)&1)*2 + ((l>>2)&1).
__device__ __forceinline__ float rs4(ull_t m[2][2], int l)
{
    bool h16 = (l & 16);
    #pragma unroll
    for (int rp = 0; rp < 2; rp++) {
        ull_t snd = h16 ? m[0][rp] : m[1][rp];
        ull_t kp  = h16 ? m[1][rp] : m[0][rp];
        m[0][rp] = add2(kp, shfl_xor64(snd, 16));
    }
    bool h8 = (l & 8);
    ull_t snd = h8 ? m[0][0] : m[0][1];
    ull_t kp  = h8 ? m[0][1] : m[0][0];
    ull_t f2 = add2(kp, shfl_xor64(snd, 8));
    float f0, f1;
    unpk(f2, f0, f1);
    bool h4 = (l & 4);
    float snf = h4 ? f0 : f1;
    float kpf = h4 ? f1 : f0;
    return kpf + __shfl_xor_sync(0xffffffffu, snf, 4);
}

// ---------------------------------------------------------------------------
// Persistent integration kernel: 128 CTAs x 512 threads, 4 rows per CTA.
// In-warp split-K (8 slices) + shuffle reduce-scatter; 3 barriers/eval;
// depth-8 rolling W2 pipeline (cross-phase wrap) and depth-4 rolling W3
// pipeline (cross-eval wrap) — every global weight load has >=350 cyc of
// issue distance before consumption.
// ---------------------------------------------------------------------------
#define SMEM_FLOATS (32768 + 512 + 512 + 1024 + 1024 + 4096 + 256 + 256 + 32 + 40)

__global__ void __launch_bounds__(NTHR, 1)
integrate_kernel(const float* __restrict__ x0,     // [512][5]
                 const float* __restrict__ W_in,   // [128][5]
                 const float* __restrict__ b_in,   // [128]
                 const float* __restrict__ b1,     // [256]
                 const float* __restrict__ b2,     // [256]
                 const float* __restrict__ W_out,  // [10][128]
                 const float* __restrict__ b_out,  // [10]
                 const float* __restrict__ ts,
                 float* __restrict__ out)          // [512][10]
{
    extern __shared__ __align__(16) float sm[];
    float* W1s  = sm;                    // 32768 : packed W1
    float* y_s  = W1s + 32768;           // 512   : y   [h=128][r=4]
    float* yt_s = y_s + 512;             // 512
    float* h1_s = yt_s + 512;            // 1024  : [c=256][r=4]
    float* h2_s = h1_s + 1024;           // 1024
    float* bm_s = h2_s + 1024;           // 4096
    float* b1_s = bm_s + 4096;           // 256
    float* b2_s = b1_s + 256;            // 256
    float* dl_s = b2_s + 256;            // 32
    int*   idx_s = (int*)(dl_s + 32);    // 40

    const int tid = threadIdx.x;
    const int r0  = blockIdx.x * RB;
    const int wrp = tid >> 5;            // warp 0..15
    const int l   = tid & 31;
    const int kq  = l >> 2;              // K-slice 0..7
    const int cgl = l & 3;               // col-group within warp

    // Final-slot coordinates after reduce-scatter
    const int ci12 = ((l >> 4) & 1) * 2 + ((l >> 3) & 1);
    const int rp12 = (l >> 2) & 1;
    const int c12  = (wrp * 4 + cgl) * 4 + ci12;        // layer-1/2 column
    const int ci3  = (l >> 4) & 1;
    const int r3   = ((l >> 3) & 1) * 2 + ((l >> 2) & 1);
    const int h3   = (wrp * 4 + cgl) * 2 + ci3;         // layer-3 column

    // Lane bases in packed layouts
    const int wb12 = (wrp * 8 + kq) * 16 + cgl * 4;     // L1/L2: + i*2048
    const int wb3  = (wrp * 8 + kq) * 8 + cgl * 2;      // L3:    + i*1024
    const int ab   = kq * 4;                            // acts:  + i*32

    // Preload smem
    for (int i = tid; i < 8192; i += NTHR)
        *(float4*)&W1s[i * 4] = *(const float4*)&g_W1p[i * 4];
    for (int i = tid; i < 4096; i += NTHR) bm_s[i] = g_bm[i];
    if (tid < 256) { b1_s[tid] = b1[tid]; b2_s[tid] = b2[tid]; }
    if (tid < 32)  dl_s[tid] = g_delta[tid];
    if (tid < 2 * NSTEP) idx_s[tid] = g_idx[tid];

    // y0 = x0 @ W_in^T + b_in   (one (h, r) per thread)
    {
        int h = tid >> 2, r = tid & 3;
        float acc = __ldg(&b_in[h]);
        #pragma unroll
        for (int d = 0; d < D_IN; d++)
            acc += __ldg(&x0[(r0 + r) * D_IN + d]) * __ldg(&W_in[h * D_IN + d]);
        y_s[tid] = acc;
    }
    const float dt = (ts[32] - ts[0]) / 20.0f;
    __syncthreads();

    // Rolling weight pipelines (initial fill)
    const float* wp2l = g_W2p + wb12;                   // static per thread
    float4 w2buf[8];
    #pragma unroll
    for (int j = 0; j < 8; j++) w2buf[j] = *(const float4*)(wp2l + j * 2048);
    float2 w3buf[4];
    {
        const float* wp30 = g_Wmp + idx_s[0] * 32768 + wb3;
        #pragma unroll
        for (int j = 0; j < 4; j++) w3buf[j] = *(const float2*)(wp30 + j * 1024);
    }

    float k1r = 0.0f;

    for (int step = 0; step < NSTEP; step++) {
        #pragma unroll 1
        for (int phase = 0; phase < 2; phase++) {
            const float* in_s = phase ? yt_s : y_s;
            const int e  = 2 * step + phase;
            const int kt = idx_s[e];
            const int en = (e + 1 < 2 * NSTEP) ? e + 1 : e;
            const float* wp3c = g_Wmp + kt * 32768 + wb3;         // current eval
            const float* wp3n = g_Wmp + idx_s[en] * 32768 + wb3;  // next eval

            // ==== Layer 1: K=128, in-warp split-8, 16 i-iters (smem w+acts) ====
            {
                ull_t acc[4][2];
                #pragma unroll
                for (int ci = 0; ci < 4; ci++) { acc[ci][0] = 0ull; acc[ci][1] = 0ull; }
                const float* wl = W1s + wb12;
                const float* ap = in_s + ab;
                #pragma unroll
                for (int i = 0; i < 16; i++) {
                    float4 w = *(const float4*)(wl + i * 2048);
                    ulonglong2 av = *(const ulonglong2*)(ap + i * 32);
                    mac4(w, av, acc);
                }
                ull_t fin = rs8(acc, l);
                float v0, v1;
                unpk(fin, v0, v1);
                float bb = b1_s[c12];
                *(float2*)&h1_s[c12 * 4 + rp12 * 2] =
                    make_float2(fmaxf(v0 + bb, 0.f), fmaxf(v1 + bb, 0.f));
            }
            __syncthreads();

            // ==== Layer 2: K=256, split-8, 32 i-iters, depth-8 rolling pipe ====
            // Refill slot (i&7) with src ((i+8)&31); iters 24-31 load next
            // phase's iters 0-7 (same static addresses) — self-refilling.
            {
                ull_t acc[4][2];
                #pragma unroll
                for (int ci = 0; ci < 4; ci++) { acc[ci][0] = 0ull; acc[ci][1] = 0ull; }
                const float* ap = h1_s + ab;
                #pragma unroll
                for (int i = 0; i < 32; i++) {
                    float4 w = w2buf[i & 7];
                    w2buf[i & 7] = *(const float4*)(wp2l + ((i + 8) & 31) * 2048);
                    ulonglong2 av = *(const ulonglong2*)(ap + i * 32);
                    mac4(w, av, acc);
                }
                ull_t fin = rs8(acc, l);
                float v0, v1;
                unpk(fin, v0, v1);
                float bb = b2_s[c12];
                *(float2*)&h2_s[c12 * 4 + rp12 * 2] =
                    make_float2(tanhf(v0 + bb), tanhf(v1 + bb));
            }
            __syncthreads();

            // ==== Layer 3: K=256, split-8, 32 i-iters, depth-4 rolling pipe ====
            // Refill slot (i&3) with src (i+4); iters 28-31 load NEXT eval's
            // iters 0-3 from wp3n (cross-eval wrap).
            {
                ull_t m[2][2];
                m[0][0] = 0ull; m[0][1] = 0ull; m[1][0] = 0ull; m[1][1] = 0ull;
                const float* ap = h2_s + ab;
                #pragma unroll
                for (int i = 0; i < 32; i++) {
                    float2 w = w3buf[i & 3];
                    if (i + 4 < 32)
                        w3buf[i & 3] = *(const float2*)(wp3c + (i + 4) * 1024);
                    else
                        w3buf[i & 3] = *(const float2*)(wp3n + (i + 4 - 32) * 1024);
                    ulonglong2 av = *(const ulonglong2*)(ap + i * 32);
                    mac2(w, av, m);
                }
                float a = rs4(m, l);
                float dl  = dl_s[kt];
                float bmv = bm_s[kt * H_DIM + h3];
                float d = (a + bmv) / dl;
                int addr = h3 * 4 + r3;
                if (phase == 0) {
                    k1r = d;
                    yt_s[addr] = y_s[addr] + dt * d;
                } else {
                    y_s[addr] = y_s[addr] + 0.5f * dt * (k1r + d);
                }
            }
            __syncthreads();
        }
    }

    // ---- Output: softmax(y @ W_out^T + b_out), 4 rows x 10 labels ----
    if (tid < RB * LAB) {
        int lab = tid % LAB, r = tid / LAB;
        float acc = __ldg(&b_out[lab]);
        for (int k = 0; k < H_DIM; k++)
            acc += y_s[k * RB + r] * __ldg(&W_out[lab * H_DIM + k]);
        h1_s[r * LAB + lab] = acc;
    }
    __syncthreads();
    if (tid < RB) {
        int r = tid;
        float mx = -1e30f;
        #pragma unroll
        for (int lq = 0; lq < LAB; lq++) mx = fmaxf(mx, h1_s[r * LAB + lq]);
        float e[LAB]; float sum = 0.f;
        #pragma unroll
        for (int lq = 0; lq < LAB; lq++) { e[lq] = expf(h1_s[r * LAB + lq] - mx); sum += e[lq]; }
        #pragma unroll
        for (int lq = 0; lq < LAB; lq++) out[(r0 + r) * LAB + lq] = e[lq] / sum;
    }
}

// ---------------------------------------------------------------------------
extern "C" void kernel_launch(void* const* d_in, const int* in_sizes, int n_in,
                              void* d_out, int out_size)
{
    const float* ts        = (const float*)d_in[0];
    const float* logsig    = (const float*)d_in[1];
    const float* x0        = (const float*)d_in[2];
    const float* intervals = (const float*)d_in[3];
    const float* W_vf1     = (const float*)d_in[4];
    const float* b_vf1     = (const float*)d_in[5];
    const float* W_vf2     = (const float*)d_in[6];
    const float* b_vf2     = (const float*)d_in[7];
    const float* W_m       = (const float*)d_in[8];
    const float* b_m       = (const float*)d_in[9];
    const float* W_in      = (const float*)d_in[10];
    const float* b_in      = (const float*)d_in[11];
    const float* W_out     = (const float*)d_in[12];
    const float* b_out     = (const float*)d_in[13];
    float* out = (float*)d_out;

    size_t smem_bytes = SMEM_FLOATS * sizeof(float);  // 162,080 B
    cudaFuncSetAttribute(integrate_kernel,
                         cudaFuncAttributeMaxDynamicSharedMemorySize,
                         (int)smem_bytes);

    setup_kernel<<<160, 256>>>(ts, intervals, W_vf1, W_vf2, logsig, W_m, b_m);
    integrate_kernel<<<NCTA, NTHR, smem_bytes>>>(x0, W_in, b_in, b_vf1, b_vf2,
                                                 W_out, b_out, ts, out);
}